// round 6
// baseline (speedup 1.0000x reference)
#include <cuda_runtime.h>
#include <math.h>
#include <stdint.h>

// Static shapes for NativeSparseCrossAttention
#define B_      2
#define N_L     128
#define D_      512
#define N_T     16384
#define D_IN    256
#define NB      256            // blocks per batch
#define BS_     64             // tokens per block
#define TOPK    16
#define RDIM    64
#define NHEAD   8
#define HD      64
#define NLAT    (B_ * N_L)     // 256

// NO __device__ globals.  All intermediates live inside d_out (per-row slots):
//   slot r = d_out[r*512 .. r*512+512)
//   phase A:  slot[g>>1][16+(g&1)*64 .. +64) = router-K vec of summary g
//   phase B:  slot[r][0:16)  = top-16 block indices (int bitcast)
//   phase C:  slot[r][16:512) = q[16:512] of row r
//   phase D:  slot[r][0:512)  = final output row r

// ---------------------------------------------------------------------------
// K1: block summary (mean of 64 tokens) + router-K projection -> slots.
__global__ __launch_bounds__(256) void nsca6_k1_summary(
    const float* __restrict__ bytes,
    const float* __restrict__ Wrk,    // [256 x 64]
    const float* __restrict__ brk,    // [64]
    float* __restrict__ dout)
{
    int g = blockIdx.x;                        // 0..511  (b*NB + blk)
    const float* base = bytes + (size_t)g * BS_ * D_IN;
    __shared__ float s[D_IN];
    int d = threadIdx.x;
    float acc = 0.f;
    #pragma unroll 8
    for (int t = 0; t < BS_; ++t) acc += base[t * D_IN + d];
    s[d] = acc * (1.0f / 64.0f);
    __syncthreads();
    if (d < RDIM) {
        float r = brk[d];
        #pragma unroll 8
        for (int k = 0; k < D_IN; ++k) r += s[k] * Wrk[k * RDIM + d];
        dout[(size_t)(g >> 1) * 512 + 16 + (g & 1) * 64 + d] = r;
    }
}

// ---------------------------------------------------------------------------
// K2: per-row router-Q + logits + top-16 -> idx into own slot [0:16).
__global__ __launch_bounds__(256) void nsca6_k2_topk(
    const float* __restrict__ latents,
    const float* __restrict__ Wrq,    // [512 x 64]
    const float* __restrict__ brq,    // [64]
    float* __restrict__ dout)
{
    int row = blockIdx.x;                      // 0..255
    int b   = row >> 7;
    int tid = threadIdx.x;
    __shared__ float lat[D_];
    __shared__ float rq[RDIM];
    __shared__ float lg[NB];
    __shared__ float mval[NB];
    __shared__ int   mind[NB];

    lat[tid]       = latents[(size_t)row * D_ + tid];
    lat[tid + 256] = latents[(size_t)row * D_ + tid + 256];
    __syncthreads();

    if (tid < RDIM) {
        float a = brq[tid];
        #pragma unroll 8
        for (int k = 0; k < D_; ++k) a += lat[k] * Wrq[k * RDIM + tid];
        rq[tid] = a;
    }
    __syncthreads();

    {
        int g = b * NB + tid;                  // summary id for this batch
        const float* rk = dout + (size_t)(g >> 1) * 512 + 16 + (g & 1) * 64;
        float a = 0.f;
        #pragma unroll 8
        for (int j = 0; j < RDIM; ++j) a += rq[j] * rk[j];
        lg[tid] = a;
    }
    __syncthreads();

    int* idx_out = (int*)dout + (size_t)row * 512;
    for (int k = 0; k < TOPK; ++k) {
        mval[tid] = lg[tid]; mind[tid] = tid;
        __syncthreads();
        for (int s = 128; s > 0; s >>= 1) {
            if (tid < s) {
                if (mval[tid + s] > mval[tid]) { mval[tid] = mval[tid + s]; mind[tid] = mind[tid + s]; }
            }
            __syncthreads();
        }
        if (tid == 0) { idx_out[k] = mind[0]; lg[mind[0]] = -INFINITY; }
        __syncthreads();
    }
}

// ---------------------------------------------------------------------------
// K3: q projection, writing q[n] for n>=16 into slots (guarded scalar stores).
__global__ __launch_bounds__(256) void nsca6_k3_qproj(
    const float* __restrict__ A,      // latents [256 x 512]
    const float* __restrict__ W,      // Wq [512 x 512]
    float* __restrict__ dout)
{
    __shared__ float As[16][33];
    int tid = threadIdx.x;
    int m0 = blockIdx.y * 16;
    int n0 = blockIdx.x * 128;
    int tx = tid & 31, ty = tid >> 5;
    int col = n0 + tx * 4;
    int r0 = ty * 2, r1 = r0 + 1;
    float a00 = 0, a01 = 0, a02 = 0, a03 = 0;
    float a10 = 0, a11 = 0, a12 = 0, a13 = 0;

    for (int k0 = 0; k0 < D_; k0 += 32) {
        int rr = tid >> 4, cc = (tid & 15) * 2;
        const float* Ar = A + (size_t)(m0 + rr) * D_ + k0;
        As[rr][cc] = Ar[cc]; As[rr][cc + 1] = Ar[cc + 1];
        __syncthreads();
        #pragma unroll
        for (int kk = 0; kk < 32; ++kk) {
            float4 wv = *reinterpret_cast<const float4*>(&W[(size_t)(k0 + kk) * D_ + col]);
            float a0 = As[r0][kk], a1 = As[r1][kk];
            a00 += a0 * wv.x; a01 += a0 * wv.y; a02 += a0 * wv.z; a03 += a0 * wv.w;
            a10 += a1 * wv.x; a11 += a1 * wv.y; a12 += a1 * wv.z; a13 += a1 * wv.w;
        }
        __syncthreads();
    }
    // guarded scalar stores: never touch columns 0..15 (idx lives there)
    {
        float* Cr = dout + (size_t)(m0 + r0) * 512 + col;
        if (col + 0 >= 16) Cr[0] = a00;
        if (col + 1 >= 16) Cr[1] = a01;
        if (col + 2 >= 16) Cr[2] = a02;
        if (col + 3 >= 16) Cr[3] = a03;
        Cr = dout + (size_t)(m0 + r1) * 512 + col;
        if (col + 0 >= 16) Cr[0] = a10;
        if (col + 1 >= 16) Cr[1] = a11;
        if (col + 2 >= 16) Cr[2] = a12;
        if (col + 3 >= 16) Cr[3] = a13;
    }
}

// ---------------------------------------------------------------------------
// K4: fused attention per row.  Reads ONLY own slot (idx + q[16:512]) plus
// pure inputs; writes ONLY own slot (final output row).  Race-free.
//  s[t,h] = x_t . U[:,h],  U[:,h] = Wk[:,h*64:+64] @ q_h
//  ctx[h] = sum_t p[t,h] x_t ; o_h = (ctx[h]/l_h) @ Wv_h ; out = o @ Wo
// smem (float offsets):
#define XS_OFF   0            // [64][260]  gathered x tile / ctx partials
#define UT_OFF   16640        // [8][260]   U, later ctx_s
#define SC_OFF   18720        // [1024][8]  latents staging, scores, later o_s
#define QS_OFF   26912        // [512]      q row
#define IL_OFF   27424        // [8]        1/l per head
#define SX_OFF   27432        // [16]       selected block ids
#define SMEM_FLOATS 27456
#define SMEM_BYTES  (SMEM_FLOATS * 4)

__global__ __launch_bounds__(256) void nsca6_k4_attn(
    const float* __restrict__ bytes,
    const float* __restrict__ latents,
    const float* __restrict__ Wq,
    const float* __restrict__ Wk,
    const float* __restrict__ Wv,
    const float* __restrict__ Wo,
    float* __restrict__ dout)
{
    extern __shared__ float sm[];
    float*  xs  = sm + XS_OFF;
    float*  Ut  = sm + UT_OFF;
    float*  sc  = sm + SC_OFF;
    float*  qs  = sm + QS_OFF;
    float*  il  = sm + IL_OFF;
    int*    sidx = (int*)(sm + SX_OFF);
    float4* xs4 = (float4*)xs;
    float4* Ut4 = (float4*)Ut;
    float4* sc4 = (float4*)sc;

    int row = blockIdx.x;
    int b   = row >> 7;
    int tid = threadIdx.x;
    int w   = tid >> 5;
    int lane = tid & 31;

    float* slot = dout + (size_t)row * 512;

    // own-slot reads: idx + q[16:512]
    if (tid < TOPK) sidx[tid] = ((const int*)slot)[tid];
    for (int i = tid; i < 496; i += 256) qs[16 + i] = slot[16 + i];
    // stage latents row in sc area (free until score pass)
    float* lat = sc;
    lat[tid]       = latents[(size_t)row * D_ + tid];
    lat[tid + 256] = latents[(size_t)row * D_ + tid + 256];
    __syncthreads();

    // recompute q[0:16] = latents_row @ Wq[:,0:16]
    if (tid < 16) {
        float a = 0.f;
        #pragma unroll 8
        for (int k = 0; k < D_; ++k) a += lat[k] * Wq[(size_t)k * D_ + tid];
        qs[tid] = a;
    }
    __syncthreads();

    // ---- U[d][h] = sum_j Wk[d][h*64+j] * q[h*64+j]   (warp w = head w)
    {
        float qx = qs[w * 64 + lane * 2];
        float qy = qs[w * 64 + lane * 2 + 1];
        for (int d0 = 0; d0 < 256; d0 += 8) {
            float a0, a1, a2, a3, a4, a5, a6, a7;
            {
                const float* Wb = Wk + (size_t)d0 * D_ + w * 64 + lane * 2;
                float2 t;
                t = *reinterpret_cast<const float2*>(Wb + 0 * D_); a0 = t.x * qx + t.y * qy;
                t = *reinterpret_cast<const float2*>(Wb + 1 * D_); a1 = t.x * qx + t.y * qy;
                t = *reinterpret_cast<const float2*>(Wb + 2 * D_); a2 = t.x * qx + t.y * qy;
                t = *reinterpret_cast<const float2*>(Wb + 3 * D_); a3 = t.x * qx + t.y * qy;
                t = *reinterpret_cast<const float2*>(Wb + 4 * D_); a4 = t.x * qx + t.y * qy;
                t = *reinterpret_cast<const float2*>(Wb + 5 * D_); a5 = t.x * qx + t.y * qy;
                t = *reinterpret_cast<const float2*>(Wb + 6 * D_); a6 = t.x * qx + t.y * qy;
                t = *reinterpret_cast<const float2*>(Wb + 7 * D_); a7 = t.x * qx + t.y * qy;
            }
            #pragma unroll
            for (int off = 16; off; off >>= 1) {
                a0 += __shfl_xor_sync(0xffffffffu, a0, off);
                a1 += __shfl_xor_sync(0xffffffffu, a1, off);
                a2 += __shfl_xor_sync(0xffffffffu, a2, off);
                a3 += __shfl_xor_sync(0xffffffffu, a3, off);
                a4 += __shfl_xor_sync(0xffffffffu, a4, off);
                a5 += __shfl_xor_sync(0xffffffffu, a5, off);
                a6 += __shfl_xor_sync(0xffffffffu, a6, off);
                a7 += __shfl_xor_sync(0xffffffffu, a7, off);
            }
            if (lane == 0) {
                float* u = Ut + w * 260 + d0;
                u[0] = a0; u[1] = a1; u[2] = a2; u[3] = a3;
                u[4] = a4; u[5] = a5; u[6] = a6; u[7] = a7;
            }
        }
    }
    __syncthreads();

    const float scale = 0.125f;         // 1/sqrt(64)
    int tokbase = b * N_T;

    // ---- score pass: 16 tiles of 64 tokens (overwrites lat staging in sc)
    int h = tid & 7, tg = tid >> 3;     // thread owns tokens tg, tg+32 for head h
    for (int c = 0; c < TOPK; ++c) {
        const float4* src = (const float4*)(bytes + (size_t)(tokbase + sidx[c] * BS_) * D_IN);
        for (int i = tid; i < 64 * 64; i += 256) {
            int t = i >> 6, c4 = i & 63;
            xs4[t * 65 + c4] = src[t * 64 + c4];
        }
        __syncthreads();
        float s0 = 0.f, s1 = 0.f;
        #pragma unroll 8
        for (int i = 0; i < 64; ++i) {
            float4 u  = Ut4[h * 65 + i];
            float4 p0 = xs4[tg * 65 + i];
            float4 p1 = xs4[(tg + 32) * 65 + i];
            s0 += p0.x * u.x + p0.y * u.y + p0.z * u.z + p0.w * u.w;
            s1 += p1.x * u.x + p1.y * u.y + p1.z * u.z + p1.w * u.w;
        }
        sc[(c * 64 + tg) * 8 + h]      = s0 * scale;
        sc[(c * 64 + tg + 32) * 8 + h] = s1 * scale;
        __syncthreads();
    }

    // ---- softmax per head (warp w handles head w); probs left unnormalized
    {
        float m = -INFINITY;
        for (int i = lane; i < 1024; i += 32) m = fmaxf(m, sc[i * 8 + w]);
        #pragma unroll
        for (int off = 16; off; off >>= 1) m = fmaxf(m, __shfl_xor_sync(0xffffffffu, m, off));
        float l = 0.f;
        for (int i = lane; i < 1024; i += 32) {
            float e = expf(sc[i * 8 + w] - m);
            sc[i * 8 + w] = e;
            l += e;
        }
        #pragma unroll
        for (int off = 16; off; off >>= 1) l += __shfl_xor_sync(0xffffffffu, l, off);
        if (lane == 0) il[w] = 1.0f / l;
    }
    __syncthreads();

    // ---- ctx pass: ctx[h][d] = sum_t p[t,h] x[t,d]
    int dq = tid & 63;                  // float4 chunk of d (0..63)
    int tp = tid >> 6;                  // token partition (0..3)
    float4 c0 = {0,0,0,0}, c1 = {0,0,0,0}, c2 = {0,0,0,0}, c3 = {0,0,0,0};
    float4 c4v = {0,0,0,0}, c5 = {0,0,0,0}, c6 = {0,0,0,0}, c7 = {0,0,0,0};

    for (int c = 0; c < TOPK; ++c) {
        const float4* src = (const float4*)(bytes + (size_t)(tokbase + sidx[c] * BS_) * D_IN);
        for (int i = tid; i < 64 * 64; i += 256) {
            int t = i >> 6, cc4 = i & 63;
            xs4[t * 65 + cc4] = src[t * 64 + cc4];
        }
        __syncthreads();
        int t0 = tp * 16;
        #pragma unroll 4
        for (int t = t0; t < t0 + 16; ++t) {
            float4 xv = xs4[t * 65 + dq];
            float4 p0 = sc4[(c * 64 + t) * 2];
            float4 p1 = sc4[(c * 64 + t) * 2 + 1];
            c0.x += p0.x*xv.x; c0.y += p0.x*xv.y; c0.z += p0.x*xv.z; c0.w += p0.x*xv.w;
            c1.x += p0.y*xv.x; c1.y += p0.y*xv.y; c1.z += p0.y*xv.z; c1.w += p0.y*xv.w;
            c2.x += p0.z*xv.x; c2.y += p0.z*xv.y; c2.z += p0.z*xv.z; c2.w += p0.z*xv.w;
            c3.x += p0.w*xv.x; c3.y += p0.w*xv.y; c3.z += p0.w*xv.z; c3.w += p0.w*xv.w;
            c4v.x += p1.x*xv.x; c4v.y += p1.x*xv.y; c4v.z += p1.x*xv.z; c4v.w += p1.x*xv.w;
            c5.x += p1.y*xv.x; c5.y += p1.y*xv.y; c5.z += p1.y*xv.z; c5.w += p1.y*xv.w;
            c6.x += p1.z*xv.x; c6.y += p1.z*xv.y; c6.z += p1.z*xv.z; c6.w += p1.z*xv.w;
            c7.x += p1.w*xv.x; c7.y += p1.w*xv.y; c7.z += p1.w*xv.z; c7.w += p1.w*xv.w;
        }
        __syncthreads();
    }

    // ---- reduce 4 token-partitions via smem (reuse xs region)
    float4* red4 = xs4;
    red4[(tp * 8 + 0) * 64 + dq] = c0;
    red4[(tp * 8 + 1) * 64 + dq] = c1;
    red4[(tp * 8 + 2) * 64 + dq] = c2;
    red4[(tp * 8 + 3) * 64 + dq] = c3;
    red4[(tp * 8 + 4) * 64 + dq] = c4v;
    red4[(tp * 8 + 5) * 64 + dq] = c5;
    red4[(tp * 8 + 6) * 64 + dq] = c6;
    red4[(tp * 8 + 7) * 64 + dq] = c7;
    __syncthreads();

    float* ctx_s = Ut;                  // reuse Ut: [8][260]
    float* redb  = xs;
    for (int i = tid; i < 2048; i += 256) {
        int hh = i >> 8, k = i & 255;
        float v = redb[(0 * 8 + hh) * 256 + k] + redb[(1 * 8 + hh) * 256 + k]
                + redb[(2 * 8 + hh) * 256 + k] + redb[(3 * 8 + hh) * 256 + k];
        ctx_s[hh * 260 + k] = v * il[hh];
    }
    __syncthreads();

    // ---- o_h[j] = sum_k ctx[h][k] * Wv[k][h*64+j]  -> o_s (reuse sc area)
    float* o_s = sc;                    // [512]
    {
        float a0 = 0.f, a1 = 0.f;
        const float* ch = ctx_s + w * 260;
        #pragma unroll 4
        for (int k = 0; k < 256; ++k) {
            float2 wv = *reinterpret_cast<const float2*>(
                &Wv[(size_t)k * D_ + w * 64 + lane * 2]);
            float cv = ch[k];
            a0 += cv * wv.x; a1 += cv * wv.y;
        }
        __syncthreads();                // ensure probs no longer needed
        o_s[w * 64 + lane * 2]     = a0;
        o_s[w * 64 + lane * 2 + 1] = a1;
    }
    __syncthreads();

    // ---- out[n] = sum_k o[k] * Wo[k][n]  -> own slot (overwrites idx+q)
    {
        float acc0 = 0.f, acc1 = 0.f;
        #pragma unroll 4
        for (int k = 0; k < 512; ++k) {
            float ov = o_s[k];
            acc0 += ov * Wo[(size_t)k * D_ + tid];
            acc1 += ov * Wo[(size_t)k * D_ + tid + 256];
        }
        slot[tid]       = acc0;
        slot[tid + 256] = acc1;
    }
}

// ---------------------------------------------------------------------------
extern "C" void kernel_launch(void* const* d_in, const int* in_sizes, int n_in,
                              void* d_out, int out_size)
{
    const float* latents = (const float*)d_in[0];
    const float* bytes   = (const float*)d_in[1];
    const float* rqw     = (const float*)d_in[2];
    const float* rqb     = (const float*)d_in[3];
    const float* rkw     = (const float*)d_in[4];
    const float* rkb     = (const float*)d_in[5];
    const float* Wq      = (const float*)d_in[6];
    const float* Wk      = (const float*)d_in[7];
    const float* Wv      = (const float*)d_in[8];
    const float* Wo      = (const float*)d_in[9];
    float* out = (float*)d_out;

    cudaFuncSetAttribute(nsca6_k4_attn,
                         cudaFuncAttributeMaxDynamicSharedMemorySize, SMEM_BYTES);

    nsca6_k1_summary<<<B_ * NB, 256>>>(bytes, rkw, rkb, out);
    nsca6_k2_topk<<<NLAT, 256>>>(latents, rqw, rqb, out);
    nsca6_k3_qproj<<<dim3(4, 16), 256>>>(latents, Wq, out);
    nsca6_k4_attn<<<NLAT, 256, SMEM_BYTES>>>(bytes, latents, Wq, Wk, Wv, Wo, out);
}